// round 12
// baseline (speedup 1.0000x reference)
#include <cuda_runtime.h>
#include <cstdint>

// ---------------------------------------------------------------------------
// HODLR linear on TF32 tensor cores (mma.sync.m16n8k8.tf32), 2-CTA/SM tiles.
//
//   repack:  us -> g_Wp [kc][64][96] (tf32-rounded, chunk-major), ds -> g_Dr,
//            vs -> g_Vr (rounded in place layout).
//   proj:    CTA = 64 tokens; per 64-k chunk GEMM X(64x64)@U(64x96); mma C
//            fragments are the HODLR accumulators, flushed at block ends.
//   expand:  CTA = (output block j, 64-token tile): K=160 GEMM
//            A=[x_j | T slices], B=[ds_j ; vs slices], + bias -> out.
//
// Both kernels: smem = 88064 B -> 2 CTAs/SM for cross-CTA latency hiding.
// Banking: A row-stride 68/164 (==4 mod 32), B row-stride 104/72 (==8 mod 32).
// ---------------------------------------------------------------------------

#define NT 256

__device__ __align__(16) float g_T [16384ull * 2048];
__device__ __align__(16) float g_Wp[64 * 6144];    // [kc][k_local(64)][96]
__device__ __align__(16) float g_Dr[64 * 4096];    // rounded ds
__device__ __align__(16) float g_Vr[6 * 65536];    // rounded vs

struct Ptr6 { const float* p[6]; };

__host__ __device__ __forceinline__ int t_off(int l) {
    const int offs[6] = {0, 32, 96, 224, 480, 992};
    return offs[l];
}

__device__ __forceinline__ uint32_t cvt_tf32(float f) {
    uint32_t u; asm("cvt.rna.tf32.f32 %0, %1;" : "=r"(u) : "f"(f)); return u;
}
__device__ __forceinline__ float round_tf32(float f) {
    uint32_t u; asm("cvt.rna.tf32.f32 %0, %1;" : "=r"(u) : "f"(f));
    return __uint_as_float(u);
}
__device__ __forceinline__ void mma_tf32(float c[4], const uint32_t a[4],
                                         uint32_t b0, uint32_t b1) {
    asm("mma.sync.aligned.m16n8k8.row.col.f32.tf32.tf32.f32 "
        "{%0,%1,%2,%3}, {%4,%5,%6,%7}, {%8,%9}, {%0,%1,%2,%3};"
        : "+f"(c[0]), "+f"(c[1]), "+f"(c[2]), "+f"(c[3])
        : "r"(a[0]), "r"(a[1]), "r"(a[2]), "r"(a[3]), "r"(b0), "r"(b1));
}
__device__ __forceinline__ uint32_t smem_u32(const void* p) {
    return (uint32_t)__cvta_generic_to_shared(p);
}
__device__ __forceinline__ void cpa(uint32_t d, const float* s) {
    asm volatile("cp.async.cg.shared.global [%0], [%1], 16;" :: "r"(d), "l"(s));
}
#define CP_COMMIT  asm volatile("cp.async.commit_group;")
#define CP_WAIT(n) asm volatile("cp.async.wait_group %0;" :: "n"(n))

// ===========================================================================
// Repack kernels
// ===========================================================================
__global__ void repack_us_k(Ptr6 us) {
    const int i = blockIdx.x * blockDim.x + threadIdx.x;   // 24576
    if (i >= 24576) return;
    const int l = i >> 12, k = i & 4095;
    const int kc = k >> 6, kl = k & 63;
    const float* s = us.p[l] + (size_t)k * 16;
    float* d = g_Wp + kc * 6144 + kl * 96 + l * 16;
#pragma unroll
    for (int r = 0; r < 16; r++) d[r] = round_tf32(s[r]);
}
__global__ void repack_ds_k(const float* __restrict__ ds) {
    const int i = blockIdx.x * blockDim.x + threadIdx.x;   // 4096 rows
    if (i >= 4096) return;
    const float* s = ds + (size_t)i * 64;
    float* d = g_Dr + (size_t)i * 64;
#pragma unroll
    for (int c = 0; c < 64; c++) d[c] = round_tf32(s[c]);
}
__global__ void repack_vs_k(Ptr6 vs) {
    const int i = blockIdx.x * blockDim.x + threadIdx.x;   // 24576
    if (i >= 24576) return;
    const int l = i >> 12, e = i & 4095;
    const float* s = vs.p[l] + (size_t)e * 16;
    float* d = g_Vr + l * 65536 + (size_t)e * 16;
#pragma unroll
    for (int r = 0; r < 16; r++) d[r] = round_tf32(s[r]);
}

// ===========================================================================
// Proj: grid 256 CTAs x 256 thr; CTA = 64 tokens, N=96, double-buffered.
// Warp (mg = wid>>1 in 0..3, ng = wid&1): rows mg*16 (1 m16), cols ng*48.
// ===========================================================================
__global__ __launch_bounds__(NT, 2) void proj_k(const float* __restrict__ x)
{
    extern __shared__ float sm[];
    const int XS = 64 * 68, WS = 64 * 104, BUF = XS + WS;   // 11008 floats

    const int tid = threadIdx.x, wid = tid >> 5, lane = tid & 31;
    const int tid4 = lane >> 2, tc = lane & 3;
    const int mg = wid >> 1, ng = wid & 1;
    const int tok0 = blockIdx.x * 64;

    float c[6][4];
#pragma unroll
    for (int nt = 0; nt < 6; nt++)
#pragma unroll
        for (int q = 0; q < 4; q++) c[nt][q] = 0.f;

    auto stage = [&](int buf, int kc) {
        float* xs = sm + buf * BUF;
        float* ws = xs + XS;
        const uint32_t xsa = smem_u32(xs), wsa = smem_u32(ws);
#pragma unroll
        for (int p = 0; p < 4; p++) {                 // x: 1024 float4
            const int idx = p * NT + tid, row = idx >> 4, f4 = idx & 15;
            cpa(xsa + (row * 68 + f4 * 4) * 4,
                x + (size_t)(tok0 + row) * 4096 + kc * 64 + f4 * 4);
        }
#pragma unroll
        for (int p = 0; p < 6; p++) {                 // w: 1536 float4
            const int idx = p * NT + tid, k = idx / 24, f4 = idx % 24;
            cpa(wsa + (k * 104 + f4 * 4) * 4,
                g_Wp + kc * 6144 + k * 96 + f4 * 4);
        }
        CP_COMMIT;
    };

    auto compute = [&](int buf) {
        const float* xs = sm + buf * BUF;
        const float* ws = xs + XS;
#pragma unroll
        for (int ks = 0; ks < 8; ks++) {
            uint32_t a[4];
            {
                const float* ab = xs + (mg * 16 + tid4) * 68 + ks * 8 + tc;
                a[0] = cvt_tf32(ab[0]);
                a[1] = cvt_tf32(ab[8 * 68]);
                a[2] = cvt_tf32(ab[4]);
                a[3] = cvt_tf32(ab[8 * 68 + 4]);
            }
#pragma unroll
            for (int nt = 0; nt < 6; nt++) {
                const float* bb = ws + (ks * 8 + tc) * 104 + ng * 48 + nt * 8 + tid4;
                const uint32_t b0 = __float_as_uint(bb[0]);
                const uint32_t b1 = __float_as_uint(bb[4 * 104]);
                mma_tf32(c[nt], a, b0, b1);
            }
        }
    };

    stage(0, 0);
    stage(1, 1);

    for (int kc = 0; kc < 64; kc++) {
        CP_WAIT(1);
        __syncthreads();
        compute(kc & 1);
        __syncthreads();
        if (kc + 2 < 64) stage(kc & 1, kc + 2);

        // flush layers whose block ends at this chunk (warp ng owns 3 layers)
#pragma unroll
        for (int lloc = 0; lloc < 3; lloc++) {
            const int l = 3 * ng + lloc;
            const int shift = 5 - l;
            if (((kc + 1) & ((1 << shift) - 1)) == 0) {
                const int b = kc >> shift;
#pragma unroll
                for (int u = 0; u < 2; u++) {
                    float* fr = c[2 * lloc + u];
                    const size_t tok = tok0 + mg * 16 + tid4;
                    float* base = g_T + tok * 2048 + t_off(l)
                                + b * 16 + 8 * u + 2 * tc;
                    *reinterpret_cast<float2*>(base) =
                        make_float2(round_tf32(fr[0]), round_tf32(fr[1]));
                    *reinterpret_cast<float2*>(base + 8 * 2048) =
                        make_float2(round_tf32(fr[2]), round_tf32(fr[3]));
                    fr[0] = fr[1] = fr[2] = fr[3] = 0.f;
                }
            }
        }
    }
}

// ===========================================================================
// Expand: grid (64 j, 256 token tiles) x 256 thr. CTA: M=64, N=64, K=160.
// Warp (mg = wid>>2 in 0..1, ng = wid&3): rows mg*32 (2 m16), cols ng*16.
// ===========================================================================
__global__ __launch_bounds__(NT, 2) void expand_k(
    const float* __restrict__ x, const float* __restrict__ bias,
    float* __restrict__ out)
{
    extern __shared__ float sm[];
    float* as = sm;              // [64][164] : cols 0..63 x, 64..159 T
    float* bs = sm + 64 * 164;   // [160][72] : rows 0..63 ds, 64..159 vs

    const int tid = threadIdx.x, wid = tid >> 5, lane = tid & 31;
    const int tid4 = lane >> 2, tc = lane & 3;
    const int mg = wid >> 2, ng = wid & 3;
    const int j = blockIdx.x, tok0 = blockIdx.y * 64;

    int pb[6], lo[6];
#pragma unroll
    for (int l = 0; l < 6; l++) {
        const int shift = 5 - l;
        pb[l] = (j >> shift) ^ 1;
        lo[l] = (j & ((1 << shift) - 1)) * 64;
    }

    const uint32_t asa = smem_u32(as), bsa = smem_u32(bs);
#pragma unroll
    for (int p = 0; p < 4; p++) {                     // x block j: 1024 f4
        const int idx = p * NT + tid, row = idx >> 4, f4 = idx & 15;
        cpa(asa + (row * 164 + f4 * 4) * 4,
            x + (size_t)(tok0 + row) * 4096 + j * 64 + f4 * 4);
    }
#pragma unroll
    for (int p = 0; p < 6; p++) {                     // T slices: 64 x 24 f4
        const int idx = p * NT + tid, tok = idx / 24, c4 = idx % 24;
        const int cc = c4 * 4, l = cc >> 4, r = cc & 15;
        cpa(asa + (tok * 164 + 64 + cc) * 4,
            g_T + (size_t)(tok0 + tok) * 2048 + t_off(l) + pb[l] * 16 + r);
    }
#pragma unroll
    for (int p = 0; p < 4; p++) {                     // ds rows 0..63: 1024 f4
        const int idx = p * NT + tid, k = idx >> 4, f4 = idx & 15;
        cpa(bsa + (k * 72 + f4 * 4) * 4, g_Dr + j * 4096 + k * 64 + f4 * 4);
    }
#pragma unroll
    for (int p = 0; p < 6; p++) {                     // vs rows 64..159
        const int idx = p * NT + tid, rr = idx >> 4, f4 = idx & 15;
        const int l = rr >> 4, r = rr & 15;
        cpa(bsa + ((64 + rr) * 72 + f4 * 4) * 4,
            g_Vr + l * 65536 + (size_t)(pb[l] * 16 + r) * (1 << (11 - l))
                 + lo[l] + f4 * 4);
    }
    CP_COMMIT;
    CP_WAIT(0);
    __syncthreads();

    float c[2][2][4];
#pragma unroll
    for (int mi = 0; mi < 2; mi++)
#pragma unroll
        for (int nt = 0; nt < 2; nt++)
#pragma unroll
            for (int q = 0; q < 4; q++) c[mi][nt][q] = 0.f;

#pragma unroll 5
    for (int ks = 0; ks < 20; ks++) {
        uint32_t a[2][4];
#pragma unroll
        for (int mi = 0; mi < 2; mi++) {
            const float* ab = as + (mg * 32 + mi * 16 + tid4) * 164 + ks * 8 + tc;
            a[mi][0] = cvt_tf32(ab[0]);
            a[mi][1] = cvt_tf32(ab[8 * 164]);
            a[mi][2] = cvt_tf32(ab[4]);
            a[mi][3] = cvt_tf32(ab[8 * 164 + 4]);
        }
#pragma unroll
        for (int nt = 0; nt < 2; nt++) {
            const float* bb = bs + (ks * 8 + tc) * 72 + ng * 16 + nt * 8 + tid4;
            const uint32_t b0 = __float_as_uint(bb[0]);
            const uint32_t b1 = __float_as_uint(bb[4 * 72]);
            mma_tf32(c[0][nt], a[0], b0, b1);
            mma_tf32(c[1][nt], a[1], b0, b1);
        }
    }

    // epilogue: bias + paired stores (cols 2tc, 2tc+1 contiguous)
#pragma unroll
    for (int nt = 0; nt < 2; nt++) {
        const int col = j * 64 + ng * 16 + nt * 8 + 2 * tc;
        const float2 bv = *reinterpret_cast<const float2*>(bias + col);
#pragma unroll
        for (int mi = 0; mi < 2; mi++) {
            const size_t row = tok0 + mg * 32 + mi * 16 + tid4;
            float2 o0, o1;
            o0.x = c[mi][nt][0] + bv.x;  o0.y = c[mi][nt][1] + bv.y;
            o1.x = c[mi][nt][2] + bv.x;  o1.y = c[mi][nt][3] + bv.y;
            *reinterpret_cast<float2*>(out + row * 4096 + col) = o0;
            *reinterpret_cast<float2*>(out + (row + 8) * 4096 + col) = o1;
        }
    }
}

// ===========================================================================
// Launch
// ===========================================================================
extern "C" void kernel_launch(void* const* d_in, const int* in_sizes, int n_in,
                              void* d_out, int out_size)
{
    (void)in_sizes; (void)n_in; (void)out_size;

    const float* x = (const float*)d_in[0];
    Ptr6 us, vs;
    for (int l = 0; l < 6; l++) {
        us.p[l] = (const float*)d_in[1 + 2 * l];
        vs.p[l] = (const float*)d_in[2 + 2 * l];
    }
    const float* ds   = (const float*)d_in[13];
    const float* bias = (const float*)d_in[14];
    float* out        = (float*)d_out;

    const int SMEM_P = 2 * (64 * 68 + 64 * 104) * (int)sizeof(float); // 88064
    const int SMEM_E = (64 * 164 + 160 * 72) * (int)sizeof(float);    // 88064
    cudaFuncSetAttribute(proj_k,
                         cudaFuncAttributeMaxDynamicSharedMemorySize, SMEM_P);
    cudaFuncSetAttribute(expand_k,
                         cudaFuncAttributeMaxDynamicSharedMemorySize, SMEM_E);

    repack_us_k<<<96, 256>>>(us);
    repack_ds_k<<<16, 256>>>(ds);
    repack_vs_k<<<96, 256>>>(vs);
    proj_k<<<256, NT, SMEM_P>>>(x);
    expand_k<<<dim3(64, 256), NT, SMEM_E>>>(x, bias, out);
}

// round 13
// speedup vs baseline: 1.5252x; 1.5252x over previous
#include <cuda_runtime.h>
#include <cstdint>

// ---------------------------------------------------------------------------
// HODLR linear on TF32 tensor cores (mma.sync.m16n8k8.tf32).
// R11 geometry (proj M=128/N=96 double-buffered; expand M=128/N=64/K=160)
// + 3-stage cp.async K-pipelining in expand:
//     group A: x block + ds        (K   0.. 63) -> compute ks 0..7
//     group B: T,vs layers 0..2    (K  64..111) -> compute ks 8..13
//     group C: T,vs layers 3..5    (K 112..159) -> compute ks 14..19
// Banking: A tiles row-stride 68/164 (==4 mod 32), B tiles 104/72 (==8 mod 32).
// ---------------------------------------------------------------------------

#define NT 256

__device__ __align__(16) float g_T [16384ull * 2048];
__device__ __align__(16) float g_Wp[64 * 6144];    // [kc][k_local(64)][96]
__device__ __align__(16) float g_Dr[64 * 4096];    // rounded ds
__device__ __align__(16) float g_Vr[6 * 65536];    // rounded vs

struct Ptr6 { const float* p[6]; };

__host__ __device__ __forceinline__ int t_off(int l) {
    const int offs[6] = {0, 32, 96, 224, 480, 992};
    return offs[l];
}

__device__ __forceinline__ uint32_t cvt_tf32(float f) {
    uint32_t u; asm("cvt.rna.tf32.f32 %0, %1;" : "=r"(u) : "f"(f)); return u;
}
__device__ __forceinline__ float round_tf32(float f) {
    uint32_t u; asm("cvt.rna.tf32.f32 %0, %1;" : "=r"(u) : "f"(f));
    return __uint_as_float(u);
}
__device__ __forceinline__ void mma_tf32(float c[4], const uint32_t a[4],
                                         uint32_t b0, uint32_t b1) {
    asm("mma.sync.aligned.m16n8k8.row.col.f32.tf32.tf32.f32 "
        "{%0,%1,%2,%3}, {%4,%5,%6,%7}, {%8,%9}, {%0,%1,%2,%3};"
        : "+f"(c[0]), "+f"(c[1]), "+f"(c[2]), "+f"(c[3])
        : "r"(a[0]), "r"(a[1]), "r"(a[2]), "r"(a[3]), "r"(b0), "r"(b1));
}
__device__ __forceinline__ uint32_t smem_u32(const void* p) {
    return (uint32_t)__cvta_generic_to_shared(p);
}
__device__ __forceinline__ void cpa(uint32_t d, const float* s) {
    asm volatile("cp.async.cg.shared.global [%0], [%1], 16;" :: "r"(d), "l"(s));
}
#define CP_COMMIT  asm volatile("cp.async.commit_group;")
#define CP_WAIT(n) asm volatile("cp.async.wait_group %0;" :: "n"(n))

// ===========================================================================
// Repack kernels
// ===========================================================================
__global__ void repack_us_k(Ptr6 us) {
    const int i = blockIdx.x * blockDim.x + threadIdx.x;   // 24576
    if (i >= 24576) return;
    const int l = i >> 12, k = i & 4095;
    const int kc = k >> 6, kl = k & 63;
    const float* s = us.p[l] + (size_t)k * 16;
    float* d = g_Wp + kc * 6144 + kl * 96 + l * 16;
#pragma unroll
    for (int r = 0; r < 16; r++) d[r] = round_tf32(s[r]);
}
__global__ void repack_ds_k(const float* __restrict__ ds) {
    const int i = blockIdx.x * blockDim.x + threadIdx.x;   // 4096 rows
    if (i >= 4096) return;
    const float* s = ds + (size_t)i * 64;
    float* d = g_Dr + (size_t)i * 64;
#pragma unroll
    for (int c = 0; c < 64; c++) d[c] = round_tf32(s[c]);
}
__global__ void repack_vs_k(Ptr6 vs) {
    const int i = blockIdx.x * blockDim.x + threadIdx.x;   // 24576
    if (i >= 24576) return;
    const int l = i >> 12, e = i & 4095;
    const float* s = vs.p[l] + (size_t)e * 16;
    float* d = g_Vr + l * 65536 + (size_t)e * 16;
#pragma unroll
    for (int r = 0; r < 16; r++) d[r] = round_tf32(s[r]);
}

// ===========================================================================
// Proj (R11): grid 128 CTAs x 256 thr; CTA = 128 tokens, N=96, dbl-buffered.
// Warp (mg = wid>>1, ng = wid&1): rows mg*32 (2 m16), cols ng*48 (6 n8).
// ===========================================================================
__global__ __launch_bounds__(NT) void proj_k(const float* __restrict__ x)
{
    extern __shared__ float sm[];
    const int XS = 128 * 68, WS = 64 * 104, BUF = XS + WS;

    const int tid = threadIdx.x, wid = tid >> 5, lane = tid & 31;
    const int tid4 = lane >> 2, tc = lane & 3;
    const int mg = wid >> 1, ng = wid & 1;
    const int tok0 = blockIdx.x * 128;

    float c[2][6][4];
#pragma unroll
    for (int mi = 0; mi < 2; mi++)
#pragma unroll
        for (int nt = 0; nt < 6; nt++)
#pragma unroll
            for (int q = 0; q < 4; q++) c[mi][nt][q] = 0.f;

    auto stage = [&](int buf, int kc) {
        float* xs = sm + buf * BUF;
        float* ws = xs + XS;
        const uint32_t xsa = smem_u32(xs), wsa = smem_u32(ws);
#pragma unroll
        for (int p = 0; p < 8; p++) {                 // x: 2048 float4
            const int idx = p * NT + tid, row = idx >> 4, f4 = idx & 15;
            cpa(xsa + (row * 68 + f4 * 4) * 4,
                x + (size_t)(tok0 + row) * 4096 + kc * 64 + f4 * 4);
        }
#pragma unroll
        for (int p = 0; p < 6; p++) {                 // w: 1536 float4
            const int idx = p * NT + tid, k = idx / 24, f4 = idx % 24;
            cpa(wsa + (k * 104 + f4 * 4) * 4,
                g_Wp + kc * 6144 + k * 96 + f4 * 4);
        }
        CP_COMMIT;
    };

    auto compute = [&](int buf) {
        const float* xs = sm + buf * BUF;
        const float* ws = xs + XS;
#pragma unroll
        for (int ks = 0; ks < 8; ks++) {
            uint32_t a[2][4];
#pragma unroll
            for (int mi = 0; mi < 2; mi++) {
                const float* ab = xs + (mg * 32 + mi * 16 + tid4) * 68 + ks * 8 + tc;
                a[mi][0] = cvt_tf32(ab[0]);
                a[mi][1] = cvt_tf32(ab[8 * 68]);
                a[mi][2] = cvt_tf32(ab[4]);
                a[mi][3] = cvt_tf32(ab[8 * 68 + 4]);
            }
#pragma unroll
            for (int nt = 0; nt < 6; nt++) {
                const float* bb = ws + (ks * 8 + tc) * 104 + ng * 48 + nt * 8 + tid4;
                const uint32_t b0 = __float_as_uint(bb[0]);
                const uint32_t b1 = __float_as_uint(bb[4 * 104]);
                mma_tf32(c[0][nt], a[0], b0, b1);
                mma_tf32(c[1][nt], a[1], b0, b1);
            }
        }
    };

    stage(0, 0);
    stage(1, 1);

    for (int kc = 0; kc < 64; kc++) {
        CP_WAIT(1);
        __syncthreads();
        compute(kc & 1);
        __syncthreads();
        if (kc + 2 < 64) stage(kc & 1, kc + 2);

        // flush layers whose block ends at this chunk (warp ng owns 3 layers)
#pragma unroll
        for (int lloc = 0; lloc < 3; lloc++) {
            const int l = 3 * ng + lloc;
            const int shift = 5 - l;
            if (((kc + 1) & ((1 << shift) - 1)) == 0) {
                const int b = kc >> shift;
#pragma unroll
                for (int mi = 0; mi < 2; mi++)
#pragma unroll
                    for (int u = 0; u < 2; u++) {
                        float* fr = c[mi][2 * lloc + u];
                        const size_t tok = tok0 + mg * 32 + mi * 16 + tid4;
                        float* base = g_T + tok * 2048 + t_off(l)
                                    + b * 16 + 8 * u + 2 * tc;
                        *reinterpret_cast<float2*>(base) =
                            make_float2(round_tf32(fr[0]), round_tf32(fr[1]));
                        *reinterpret_cast<float2*>(base + 8 * 2048) =
                            make_float2(round_tf32(fr[2]), round_tf32(fr[3]));
                        fr[0] = fr[1] = fr[2] = fr[3] = 0.f;
                    }
            }
        }
    }
}

// ===========================================================================
// Expand: grid (64 j, 128 token tiles) x 256 thr. CTA: M=128, N=64, K=160.
// 3-stage cp.async pipeline over K. Warp (mg, ng): rows mg*32, cols ng*32.
// ===========================================================================
__global__ __launch_bounds__(NT) void expand_k(
    const float* __restrict__ x, const float* __restrict__ bias,
    float* __restrict__ out)
{
    extern __shared__ float sm[];
    float* as = sm;               // [128][164] : cols 0..63 x, 64..159 T
    float* bs = sm + 128 * 164;   // [160][72]  : rows 0..63 ds, 64..159 vs

    const int tid = threadIdx.x, wid = tid >> 5, lane = tid & 31;
    const int tid4 = lane >> 2, tc = lane & 3;
    const int mg = wid >> 1, ng = wid & 1;
    const int j = blockIdx.x, tok0 = blockIdx.y * 128;

    int pb[6], lo[6];
#pragma unroll
    for (int l = 0; l < 6; l++) {
        const int shift = 5 - l;
        pb[l] = (j >> shift) ^ 1;
        lo[l] = (j & ((1 << shift) - 1)) * 64;
    }

    const uint32_t asa = smem_u32(as), bsa = smem_u32(bs);

    // ---- group A: x block (K cols 0..63) + ds (rows 0..63) ----
#pragma unroll
    for (int p = 0; p < 8; p++) {
        const int idx = p * NT + tid, row = idx >> 4, f4 = idx & 15;
        cpa(asa + (row * 164 + f4 * 4) * 4,
            x + (size_t)(tok0 + row) * 4096 + j * 64 + f4 * 4);
    }
#pragma unroll
    for (int p = 0; p < 4; p++) {
        const int idx = p * NT + tid, k = idx >> 4, f4 = idx & 15;
        cpa(bsa + (k * 72 + f4 * 4) * 4, g_Dr + j * 4096 + k * 64 + f4 * 4);
    }
    CP_COMMIT;

    // ---- group B: T + vs, layers 0..2 (K 64..111) ----
#pragma unroll
    for (int p = 0; p < 6; p++) {          // T cols 64..111 : 128 tok x 12 f4
        const int idx = p * NT + tid, tok = idx / 12, c4 = idx % 12;
        const int cc = c4 * 4, l = cc >> 4, r = cc & 15;
        cpa(asa + (tok * 164 + 64 + cc) * 4,
            g_T + (size_t)(tok0 + tok) * 2048 + t_off(l) + pb[l] * 16 + r);
    }
#pragma unroll
    for (int p = 0; p < 3; p++) {          // vs rows 64..111 : 48 x 16 f4
        const int idx = p * NT + tid, rr = idx >> 4, f4 = idx & 15;
        const int l = rr >> 4, r = rr & 15;
        cpa(bsa + ((64 + rr) * 72 + f4 * 4) * 4,
            g_Vr + l * 65536 + (size_t)(pb[l] * 16 + r) * (1 << (11 - l))
                 + lo[l] + f4 * 4);
    }
    CP_COMMIT;

    // ---- group C: T + vs, layers 3..5 (K 112..159) ----
#pragma unroll
    for (int p = 0; p < 6; p++) {
        const int idx = p * NT + tid, tok = idx / 12, c4 = 12 + idx % 12;
        const int cc = c4 * 4, l = cc >> 4, r = cc & 15;
        cpa(asa + (tok * 164 + 64 + cc) * 4,
            g_T + (size_t)(tok0 + tok) * 2048 + t_off(l) + pb[l] * 16 + r);
    }
#pragma unroll
    for (int p = 0; p < 3; p++) {
        const int idx = p * NT + tid, rr = 48 + (idx >> 4), f4 = idx & 15;
        const int l = rr >> 4, r = rr & 15;
        cpa(bsa + ((64 + rr) * 72 + f4 * 4) * 4,
            g_Vr + l * 65536 + (size_t)(pb[l] * 16 + r) * (1 << (11 - l))
                 + lo[l] + f4 * 4);
    }
    CP_COMMIT;

    float c[2][4][4];
#pragma unroll
    for (int mi = 0; mi < 2; mi++)
#pragma unroll
        for (int nt = 0; nt < 4; nt++)
#pragma unroll
            for (int q = 0; q < 4; q++) c[mi][nt][q] = 0.f;

    auto do_ks = [&](int ks) {
        uint32_t a[2][4];
#pragma unroll
        for (int mi = 0; mi < 2; mi++) {
            const float* ab = as + (mg * 32 + mi * 16 + tid4) * 164 + ks * 8 + tc;
            a[mi][0] = cvt_tf32(ab[0]);
            a[mi][1] = cvt_tf32(ab[8 * 164]);
            a[mi][2] = cvt_tf32(ab[4]);
            a[mi][3] = cvt_tf32(ab[8 * 164 + 4]);
        }
#pragma unroll
        for (int nt = 0; nt < 4; nt++) {
            const float* bb = bs + (ks * 8 + tc) * 72 + ng * 32 + nt * 8 + tid4;
            const uint32_t b0 = __float_as_uint(bb[0]);
            const uint32_t b1 = __float_as_uint(bb[4 * 72]);
            mma_tf32(c[0][nt], a[0], b0, b1);
            mma_tf32(c[1][nt], a[1], b0, b1);
        }
    };

    // phase 1: group A resident (2 groups may still be in flight)
    CP_WAIT(2);
    __syncthreads();
#pragma unroll
    for (int ks = 0; ks < 8; ks++) do_ks(ks);

    // phase 2: group B resident
    CP_WAIT(1);
    __syncthreads();
#pragma unroll
    for (int ks = 8; ks < 14; ks++) do_ks(ks);

    // phase 3: all resident
    CP_WAIT(0);
    __syncthreads();
#pragma unroll
    for (int ks = 14; ks < 20; ks++) do_ks(ks);

    // epilogue: bias + paired stores (cols 2tc, 2tc+1 contiguous)
#pragma unroll
    for (int nt = 0; nt < 4; nt++) {
        const int col = j * 64 + ng * 32 + nt * 8 + 2 * tc;
        const float2 bv = *reinterpret_cast<const float2*>(bias + col);
#pragma unroll
        for (int mi = 0; mi < 2; mi++) {
            const size_t row = tok0 + mg * 32 + mi * 16 + tid4;
            float2 o0, o1;
            o0.x = c[mi][nt][0] + bv.x;  o0.y = c[mi][nt][1] + bv.y;
            o1.x = c[mi][nt][2] + bv.x;  o1.y = c[mi][nt][3] + bv.y;
            *reinterpret_cast<float2*>(out + row * 4096 + col) = o0;
            *reinterpret_cast<float2*>(out + (row + 8) * 4096 + col) = o1;
        }
    }
}

// ===========================================================================
// Launch
// ===========================================================================
extern "C" void kernel_launch(void* const* d_in, const int* in_sizes, int n_in,
                              void* d_out, int out_size)
{
    (void)in_sizes; (void)n_in; (void)out_size;

    const float* x = (const float*)d_in[0];
    Ptr6 us, vs;
    for (int l = 0; l < 6; l++) {
        us.p[l] = (const float*)d_in[1 + 2 * l];
        vs.p[l] = (const float*)d_in[2 + 2 * l];
    }
    const float* ds   = (const float*)d_in[13];
    const float* bias = (const float*)d_in[14];
    float* out        = (float*)d_out;

    const int SMEM_P = 2 * (128 * 68 + 64 * 104) * (int)sizeof(float); // 122880
    const int SMEM_E = (128 * 164 + 160 * 72) * (int)sizeof(float);    // 130048
    cudaFuncSetAttribute(proj_k,
                         cudaFuncAttributeMaxDynamicSharedMemorySize, SMEM_P);
    cudaFuncSetAttribute(expand_k,
                         cudaFuncAttributeMaxDynamicSharedMemorySize, SMEM_E);

    repack_us_k<<<96, 256>>>(us);
    repack_ds_k<<<16, 256>>>(ds);
    repack_vs_k<<<96, 256>>>(vs);
    proj_k<<<128, NT, SMEM_P>>>(x);
    expand_k<<<dim3(64, 128), NT, SMEM_E>>>(x, bias, out);
}

// round 14
// speedup vs baseline: 2.1065x; 1.3811x over previous
#include <cuda_runtime.h>
#include <cuda_fp16.h>
#include <cstdint>

// ---------------------------------------------------------------------------
// HODLR linear on fp16 tensor cores (mma.sync.m16n8k16.f16, f32 accum).
//
//   repack: us -> g_Wh [kc][n=96][k=64] fp16 (transposed, chunk-major)
//           ds -> g_Dh [j][n=64][k=64] fp16 (transposed)
//           vs -> g_Vh [l][(block*cl+col)][r=16] fp16 (transposed)
//   proj:   CTA = 128 tokens, N=96; per 64-k chunk GEMM; A = f32 x smem tile
//           converted to fp16 fragments on the fly; C frags are the HODLR
//           accumulators, flushed (fp16) to g_T at block boundaries.
//   expand: CTA = (j, 128 tokens): K=160 GEMM, A=[x f32 | T fp16],
//           B=[ds ; vs] fp16 [n][k]; 3-stage cp.async K-pipeline; 2 CTAs/SM.
// ---------------------------------------------------------------------------

#define NT 256

__device__ __align__(16) __half g_T [16384ull * 2048];  // 64 MB scratch
__device__ __align__(16) __half g_Wh[64 * 6144];         // [kc][n96][k64]
__device__ __align__(16) __half g_Dh[64 * 4096];         // [j][n64][k64]
__device__ __align__(16) __half g_Vh[6 * 65536];         // [l][e][r16]

struct Ptr6 { const float* p[6]; };

__host__ __device__ __forceinline__ int t_off(int l) {
    const int offs[6] = {0, 32, 96, 224, 480, 992};
    return offs[l];
}

__device__ __forceinline__ uint32_t pack_h2(float lo, float hi) {
    __half2 h = __floats2half2_rn(lo, hi);
    return *reinterpret_cast<uint32_t*>(&h);
}
__device__ __forceinline__ void mma16(float c[4], const uint32_t a[4],
                                      uint32_t b0, uint32_t b1) {
    asm("mma.sync.aligned.m16n8k16.row.col.f32.f16.f16.f32 "
        "{%0,%1,%2,%3}, {%4,%5,%6,%7}, {%8,%9}, {%0,%1,%2,%3};"
        : "+f"(c[0]), "+f"(c[1]), "+f"(c[2]), "+f"(c[3])
        : "r"(a[0]), "r"(a[1]), "r"(a[2]), "r"(a[3]), "r"(b0), "r"(b1));
}
__device__ __forceinline__ uint32_t smem_u32(const void* p) {
    return (uint32_t)__cvta_generic_to_shared(p);
}
__device__ __forceinline__ void cpa(uint32_t d, const void* s) {
    asm volatile("cp.async.cg.shared.global [%0], [%1], 16;" :: "r"(d), "l"(s));
}
#define CP_COMMIT  asm volatile("cp.async.commit_group;")
#define CP_WAIT(n) asm volatile("cp.async.wait_group %0;" :: "n"(n))

// ===========================================================================
// Repack kernels (tiny; transpose + fp16 round)
// ===========================================================================
__global__ void repack_us_k(Ptr6 us) {
    const int i = blockIdx.x * blockDim.x + threadIdx.x;   // 6144 = 64kc x 96n
    if (i >= 6144) return;
    const int kc = i / 96, n = i % 96, l = n >> 4, r = n & 15;
    __half* d = g_Wh + kc * 6144 + n * 64;
    const float* s = us.p[l] + ((size_t)kc * 64) * 16 + r;
#pragma unroll
    for (int kl = 0; kl < 64; kl++) d[kl] = __float2half_rn(s[kl * 16]);
}
__global__ void repack_ds_k(const float* __restrict__ ds) {
    const int i = blockIdx.x * blockDim.x + threadIdx.x;   // 4096 = 64j x 64n
    if (i >= 4096) return;
    const int j = i >> 6, n = i & 63;
    __half* d = g_Dh + j * 4096 + n * 64;
    const float* s = ds + (size_t)j * 4096 + n;
#pragma unroll
    for (int k = 0; k < 64; k++) d[k] = __float2half_rn(s[k * 64]);
}
__global__ void repack_vs_k(Ptr6 vs) {
    const int i = blockIdx.x * blockDim.x + threadIdx.x;   // 24576 = 6l x 4096e
    if (i >= 24576) return;
    const int l = i >> 12, e = i & 4095;
    const int cl = 1 << (11 - l);
    const int blk = e >> (11 - l), col = e & (cl - 1);
    __half* d = g_Vh + l * 65536 + e * 16;
    const float* s = vs.p[l] + ((size_t)blk * 16) * cl + col;
#pragma unroll
    for (int r = 0; r < 16; r++) d[r] = __float2half_rn(s[(size_t)r * cl]);
}

// ===========================================================================
// Proj: grid 128 CTAs x 256 thr; CTA = 128 tokens, N=96, double-buffered.
// Warp (mg = wid>>1, ng = wid&1): rows mg*32 (2 m16), cols ng*48 (6 n8).
// Per buffer: xs f32 [128][72] (36864 B) + ws half [96][72] (13824 B).
// ===========================================================================
__global__ __launch_bounds__(NT) void proj_k(const float* __restrict__ x)
{
    extern __shared__ char smc[];
    const int XSB = 128 * 72 * 4, WSB = 96 * 72 * 2, BUF = XSB + WSB;

    const int tid = threadIdx.x, wid = tid >> 5, lane = tid & 31;
    const int tid4 = lane >> 2, tc = lane & 3;
    const int mg = wid >> 1, ng = wid & 1;
    const int tok0 = blockIdx.x * 128;

    float c[2][6][4];
#pragma unroll
    for (int mi = 0; mi < 2; mi++)
#pragma unroll
        for (int nt = 0; nt < 6; nt++)
#pragma unroll
            for (int q = 0; q < 4; q++) c[mi][nt][q] = 0.f;

    auto stage = [&](int buf, int kc) {
        float* xs = (float*)(smc + buf * BUF);
        __half* ws = (__half*)(smc + buf * BUF + XSB);
#pragma unroll
        for (int p = 0; p < 8; p++) {                 // x: 2048 f4
            const int idx = p * NT + tid, row = idx >> 4, f4 = idx & 15;
            cpa(smem_u32(xs + row * 72 + f4 * 4),
                x + (size_t)(tok0 + row) * 4096 + kc * 64 + f4 * 4);
        }
#pragma unroll
        for (int p = 0; p < 3; p++) {                 // w: 96n x 8 (16B)
            const int idx = p * NT + tid, n = idx >> 3, f8 = idx & 7;
            cpa(smem_u32(ws + n * 72 + f8 * 8),
                g_Wh + kc * 6144 + n * 64 + f8 * 8);
        }
        CP_COMMIT;
    };

    auto compute = [&](int buf) {
        const float* xs = (const float*)(smc + buf * BUF);
        const __half* ws = (const __half*)(smc + buf * BUF + XSB);
#pragma unroll
        for (int ks = 0; ks < 4; ks++) {              // K16 steps
            uint32_t a[2][4];
#pragma unroll
            for (int mi = 0; mi < 2; mi++) {
                const float* ab = xs + (mg * 32 + mi * 16 + tid4) * 72
                                + ks * 16 + 2 * tc;
                float2 f;
                f = *(const float2*)(ab);              a[mi][0] = pack_h2(f.x, f.y);
                f = *(const float2*)(ab + 8 * 72);     a[mi][1] = pack_h2(f.x, f.y);
                f = *(const float2*)(ab + 8);          a[mi][2] = pack_h2(f.x, f.y);
                f = *(const float2*)(ab + 8 * 72 + 8); a[mi][3] = pack_h2(f.x, f.y);
            }
#pragma unroll
            for (int nt = 0; nt < 6; nt++) {
                const __half* bb = ws + (ng * 48 + nt * 8 + tid4) * 72
                                 + ks * 16 + 2 * tc;
                const uint32_t b0 = *(const uint32_t*)bb;
                const uint32_t b1 = *(const uint32_t*)(bb + 8);
                mma16(c[0][nt], a[0], b0, b1);
                mma16(c[1][nt], a[1], b0, b1);
            }
        }
    };

    stage(0, 0);
    stage(1, 1);

    for (int kc = 0; kc < 64; kc++) {
        CP_WAIT(1);
        __syncthreads();
        compute(kc & 1);
        __syncthreads();
        if (kc + 2 < 64) stage(kc & 1, kc + 2);

        // flush layers whose block ends at this chunk (warp ng owns 3 layers)
#pragma unroll
        for (int lloc = 0; lloc < 3; lloc++) {
            const int l = 3 * ng + lloc;
            const int shift = 5 - l;
            if (((kc + 1) & ((1 << shift) - 1)) == 0) {
                const int b = kc >> shift;
#pragma unroll
                for (int mi = 0; mi < 2; mi++)
#pragma unroll
                    for (int u = 0; u < 2; u++) {
                        float* fr = c[mi][2 * lloc + u];
                        const size_t tok = tok0 + mg * 32 + mi * 16 + tid4;
                        const int off = t_off(l) + b * 16 + 8 * u + 2 * tc;
                        *(uint32_t*)&g_T[tok * 2048 + off] =
                            pack_h2(fr[0], fr[1]);
                        *(uint32_t*)&g_T[(tok + 8) * 2048 + off] =
                            pack_h2(fr[2], fr[3]);
                        fr[0] = fr[1] = fr[2] = fr[3] = 0.f;
                    }
            }
        }
    }
}

// ===========================================================================
// Expand: grid (64 j, 128 tiles) x 256 thr. M=128, N=64, K=160; 2 CTAs/SM.
// smem: xs f32 [128][72] | asT half [128][104] | bs half [64][168] = 84992 B.
// 3-stage pipeline: A = x+ds (ks 0..3) ; B = l0..2 (ks 4..6) ; C = l3..5.
// ===========================================================================
__global__ __launch_bounds__(NT, 2) void expand_k(
    const float* __restrict__ x, const float* __restrict__ bias,
    float* __restrict__ out)
{
    extern __shared__ char smc[];
    float* xs  = (float*)smc;                       // [128][72] f32
    __half* asT = (__half*)(smc + 36864);           // [128][104] half
    __half* bs  = (__half*)(smc + 63488);           // [64][168] half

    const int tid = threadIdx.x, wid = tid >> 5, lane = tid & 31;
    const int tid4 = lane >> 2, tc = lane & 3;
    const int mg = wid >> 1, ng = wid & 1;
    const int j = blockIdx.x, tok0 = blockIdx.y * 128;

    int pb[6], lo[6];
#pragma unroll
    for (int l = 0; l < 6; l++) {
        const int shift = 5 - l;
        pb[l] = (j >> shift) ^ 1;
        lo[l] = (j & ((1 << shift) - 1)) * 64;
    }

    // ---- group A: x block (f32) + ds rows ----
#pragma unroll
    for (int p = 0; p < 8; p++) {
        const int idx = p * NT + tid, row = idx >> 4, f4 = idx & 15;
        cpa(smem_u32(xs + row * 72 + f4 * 4),
            x + (size_t)(tok0 + row) * 4096 + j * 64 + f4 * 4);
    }
#pragma unroll
    for (int p = 0; p < 2; p++) {                   // 64n x 8 seg
        const int idx = p * NT + tid, n = idx >> 3, f8 = idx & 7;
        cpa(smem_u32(bs + n * 168 + f8 * 8), g_Dh + j * 4096 + n * 64 + f8 * 8);
    }
    CP_COMMIT;

    // ---- group B: T + vs, layers 0..2 ----
#pragma unroll
    for (int p = 0; p < 3; p++) {                   // T: 128 tok x 3l x 2seg
        const int idx = p * NT + tid, tok = idx / 6, q = idx % 6;
        const int l = q >> 1, s = (q & 1) * 8;
        cpa(smem_u32(asT + tok * 104 + l * 16 + s),
            g_T + (size_t)(tok0 + tok) * 2048 + t_off(l) + pb[l] * 16 + s);
    }
#pragma unroll
    for (int p = 0; p < 2; p++) {                   // vs: 64n x 3l x 2seg=384
        const int idx = p * NT + tid;
        if (idx < 384) {
            const int n = idx / 6, q = idx % 6, l = q >> 1, s = (q & 1) * 8;
            const int e = pb[l] * (1 << (11 - l)) + lo[l] + n;
            cpa(smem_u32(bs + n * 168 + 64 + l * 16 + s),
                g_Vh + l * 65536 + (size_t)e * 16 + s);
        }
    }
    CP_COMMIT;

    // ---- group C: T + vs, layers 3..5 ----
#pragma unroll
    for (int p = 0; p < 3; p++) {
        const int idx = p * NT + tid, tok = idx / 6, q = idx % 6;
        const int l = 3 + (q >> 1), s = (q & 1) * 8;
        cpa(smem_u32(asT + tok * 104 + 48 + (q >> 1) * 16 + s),
            g_T + (size_t)(tok0 + tok) * 2048 + t_off(l) + pb[l] * 16 + s);
    }
#pragma unroll
    for (int p = 0; p < 2; p++) {
        const int idx = p * NT + tid;
        if (idx < 384) {
            const int n = idx / 6, q = idx % 6, l = 3 + (q >> 1), s = (q & 1) * 8;
            const int e = pb[l] * (1 << (11 - l)) + lo[l] + n;
            cpa(smem_u32(bs + n * 168 + 112 + (q >> 1) * 16 + s),
                g_Vh + l * 65536 + (size_t)e * 16 + s);
        }
    }
    CP_COMMIT;

    float c[2][4][4];
#pragma unroll
    for (int mi = 0; mi < 2; mi++)
#pragma unroll
        for (int nt = 0; nt < 4; nt++)
#pragma unroll
            for (int q = 0; q < 4; q++) c[mi][nt][q] = 0.f;

    auto bfrags = [&](int k, int nt, uint32_t& b0, uint32_t& b1) {
        const __half* bb = bs + (ng * 32 + nt * 8 + tid4) * 168 + k + 2 * tc;
        b0 = *(const uint32_t*)bb;
        b1 = *(const uint32_t*)(bb + 8);
    };

    auto do_ks_x = [&](int ks) {                    // A from f32 x tile
        uint32_t a[2][4];
#pragma unroll
        for (int mi = 0; mi < 2; mi++) {
            const float* ab = xs + (mg * 32 + mi * 16 + tid4) * 72
                            + ks * 16 + 2 * tc;
            float2 f;
            f = *(const float2*)(ab);              a[mi][0] = pack_h2(f.x, f.y);
            f = *(const float2*)(ab + 8 * 72);     a[mi][1] = pack_h2(f.x, f.y);
            f = *(const float2*)(ab + 8);          a[mi][2] = pack_h2(f.x, f.y);
            f = *(const float2*)(ab + 8 * 72 + 8); a[mi][3] = pack_h2(f.x, f.y);
        }
#pragma unroll
        for (int nt = 0; nt < 4; nt++) {
            uint32_t b0, b1;
            bfrags(ks * 16, nt, b0, b1);
            mma16(c[0][nt], a[0], b0, b1);
            mma16(c[1][nt], a[1], b0, b1);
        }
    };

    auto do_ks_T = [&](int ks) {                    // A from fp16 T tile
        const int kloc = (ks - 4) * 16;
        uint32_t a[2][4];
#pragma unroll
        for (int mi = 0; mi < 2; mi++) {
            const __half* ab = asT + (mg * 32 + mi * 16 + tid4) * 104
                             + kloc + 2 * tc;
            a[mi][0] = *(const uint32_t*)ab;
            a[mi][1] = *(const uint32_t*)(ab + 8 * 104);
            a[mi][2] = *(const uint32_t*)(ab + 8);
            a[mi][3] = *(const uint32_t*)(ab + 8 * 104 + 8);
        }
#pragma unroll
        for (int nt = 0; nt < 4; nt++) {
            uint32_t b0, b1;
            bfrags(64 + kloc, nt, b0, b1);
            mma16(c[0][nt], a[0], b0, b1);
            mma16(c[1][nt], a[1], b0, b1);
        }
    };

    CP_WAIT(2);
    __syncthreads();
#pragma unroll
    for (int ks = 0; ks < 4; ks++) do_ks_x(ks);

    CP_WAIT(1);
    __syncthreads();
#pragma unroll
    for (int ks = 4; ks < 7; ks++) do_ks_T(ks);

    CP_WAIT(0);
    __syncthreads();
#pragma unroll
    for (int ks = 7; ks < 10; ks++) do_ks_T(ks);

    // epilogue: bias + paired stores (cols 2tc, 2tc+1 contiguous)
#pragma unroll
    for (int nt = 0; nt < 4; nt++) {
        const int col = j * 64 + ng * 32 + nt * 8 + 2 * tc;
        const float2 bv = *reinterpret_cast<const float2*>(bias + col);
#pragma unroll
        for (int mi = 0; mi < 2; mi++) {
            const size_t row = tok0 + mg * 32 + mi * 16 + tid4;
            float2 o0, o1;
            o0.x = c[mi][nt][0] + bv.x;  o0.y = c[mi][nt][1] + bv.y;
            o1.x = c[mi][nt][2] + bv.x;  o1.y = c[mi][nt][3] + bv.y;
            *reinterpret_cast<float2*>(out + row * 4096 + col) = o0;
            *reinterpret_cast<float2*>(out + (row + 8) * 4096 + col) = o1;
        }
    }
}

// ===========================================================================
// Launch
// ===========================================================================
extern "C" void kernel_launch(void* const* d_in, const int* in_sizes, int n_in,
                              void* d_out, int out_size)
{
    (void)in_sizes; (void)n_in; (void)out_size;

    const float* x = (const float*)d_in[0];
    Ptr6 us, vs;
    for (int l = 0; l < 6; l++) {
        us.p[l] = (const float*)d_in[1 + 2 * l];
        vs.p[l] = (const float*)d_in[2 + 2 * l];
    }
    const float* ds   = (const float*)d_in[13];
    const float* bias = (const float*)d_in[14];
    float* out        = (float*)d_out;

    const int SMEM_P = 2 * (128 * 72 * 4 + 96 * 72 * 2);   // 101376 B
    const int SMEM_E = 36864 + 26624 + 21504;              // 84992 B
    cudaFuncSetAttribute(proj_k,
                         cudaFuncAttributeMaxDynamicSharedMemorySize, SMEM_P);
    cudaFuncSetAttribute(expand_k,
                         cudaFuncAttributeMaxDynamicSharedMemorySize, SMEM_E);

    repack_us_k<<<24, 256>>>(us);
    repack_ds_k<<<16, 256>>>(ds);
    repack_vs_k<<<96, 256>>>(vs);
    proj_k<<<128, NT, SMEM_P>>>(x);
    expand_k<<<dim3(64, 128), NT, SMEM_E>>>(x, bias, out);
}